// round 6
// baseline (speedup 1.0000x reference)
#include <cuda_runtime.h>
#include <cuda_fp16.h>
#include <cstdint>

// ===================== problem constants =====================
constexpr int B_  = 8;
constexpr int LQ_ = 2048;
constexpr int LK_ = 2048;
constexpr int D_  = 128;

constexpr int BM = 128;    // q rows per CTA
constexpr int BN = 64;     // kv rows per iteration
constexpr int PITCH = 136; // smem row pitch in fp16 elems (128 + 8 pad)
constexpr int NSPLIT = 2;  // kv split factor
constexpr int NT_CTA = LK_ / BN / NSPLIT; // 16 kv tiles per CTA

constexpr float SCALE = 0.08838834764831845f; // 1/sqrt(128)
constexpr float HALF_SCALE = 0.5f * SCALE;    // for sigmoid-via-tanh

constexpr int Q_ELEMS     = BM * PITCH;            // 17408
constexpr int KV_ELEMS    = BN * PITCH;            // 8704
constexpr int STAGE_ELEMS = 2 * KV_ELEMS;          // K,V = 17408
constexpr int SMEM_ELEMS  = Q_ELEMS + 2 * STAGE_ELEMS; // 52224
constexpr int SMEM_BYTES  = SMEM_ELEMS * 2;        // 104448 -> 2 CTAs/SM

constexpr int PART_N = B_ * LQ_ * D_;              // elems per split partial

// ===================== device scratch =====================
__device__ __half g_q[B_ * LQ_ * D_];
__device__ __half g_k[B_ * LK_ * D_];
__device__ __half g_v[B_ * LK_ * D_];
__device__ float  g_part[NSPLIT * PART_N];         // partial O per kv-split

// ===================== small asm helpers =====================
__device__ __forceinline__ void cp_async16(uint32_t dst, const void* src) {
    asm volatile("cp.async.cg.shared.global [%0], [%1], 16;" :: "r"(dst), "l"(src));
}
__device__ __forceinline__ void cp_commit() {
    asm volatile("cp.async.commit_group;");
}
template <int N>
__device__ __forceinline__ void cp_wait() {
    asm volatile("cp.async.wait_group %0;" :: "n"(N));
}
__device__ __forceinline__ void ldsm4(uint32_t* r, uint32_t addr) {
    asm volatile("ldmatrix.sync.aligned.m8n8.x4.shared.b16 {%0,%1,%2,%3}, [%4];"
                 : "=r"(r[0]), "=r"(r[1]), "=r"(r[2]), "=r"(r[3]) : "r"(addr));
}
__device__ __forceinline__ void ldsm4t(uint32_t* r, uint32_t addr) {
    asm volatile("ldmatrix.sync.aligned.m8n8.x4.trans.shared.b16 {%0,%1,%2,%3}, [%4];"
                 : "=r"(r[0]), "=r"(r[1]), "=r"(r[2]), "=r"(r[3]) : "r"(addr));
}
__device__ __forceinline__ void mma16816(float* c, const uint32_t* a, uint32_t b0, uint32_t b1) {
    asm volatile(
        "mma.sync.aligned.m16n8k16.row.col.f32.f16.f16.f32 "
        "{%0,%1,%2,%3}, {%4,%5,%6,%7}, {%8,%9}, {%0,%1,%2,%3};"
        : "+f"(c[0]), "+f"(c[1]), "+f"(c[2]), "+f"(c[3])
        : "r"(a[0]), "r"(a[1]), "r"(a[2]), "r"(a[3]), "r"(b0), "r"(b1));
}
// sigmoid(s*SCALE) = 0.5*tanh(s*SCALE/2) + 0.5  -- single MUFU op
__device__ __forceinline__ float sigmoid_fast(float s) {
    float t;
    asm("tanh.approx.f32 %0, %1;" : "=f"(t) : "f"(s * HALF_SCALE));
    return fmaf(t, 0.5f, 0.5f);
}
__device__ __forceinline__ uint32_t pack2h(float x, float y) {
    __half2 h = __floats2half2_rn(x, y);
    return *reinterpret_cast<uint32_t*>(&h);
}

// ===================== prep: fp32 -> fp16 =====================
__global__ void split_kernel(const float* __restrict__ q,
                             const float* __restrict__ k,
                             const float* __restrict__ v) {
    const int t = blockIdx.y;
    const float* s = (t == 0) ? q : (t == 1) ? k : v;
    __half* H = (t == 0) ? g_q : (t == 1) ? g_k : g_v;
    const int i = (blockIdx.x * blockDim.x + threadIdx.x) * 4;
    float4 x = *reinterpret_cast<const float4*>(s + i);
    reinterpret_cast<__half2*>(H + i)[0] = __floats2half2_rn(x.x, x.y);
    reinterpret_cast<__half2*>(H + i)[1] = __floats2half2_rn(x.z, x.w);
}

// ===================== final reduce: out = part0 + part1 =====================
__global__ void reduce_kernel(float* __restrict__ out) {
    const int i = (blockIdx.x * blockDim.x + threadIdx.x) * 4;
    float4 a = *reinterpret_cast<const float4*>(g_part + i);
    float4 b = *reinterpret_cast<const float4*>(g_part + PART_N + i);
    *reinterpret_cast<float4*>(out + i) =
        make_float4(a.x + b.x, a.y + b.y, a.z + b.z, a.w + b.w);
}

// ===================== kv tile loader (K+V, 64 rows each) =====================
__device__ __forceinline__ void load_kv(uint32_t smb, int b, int kt, int stg, int tid) {
    const size_t base = ((size_t)b * LK_ + (size_t)kt * BN) * D_;
    const __half* gs[2] = { g_k + base, g_v + base };
#pragma unroll
    for (int a = 0; a < 2; a++) {
#pragma unroll
        for (int tt = 0; tt < 4; tt++) {
            int idx = tt * 256 + tid;
            int row = idx >> 4, c = idx & 15;
            cp_async16(smb + (uint32_t)((Q_ELEMS + stg * STAGE_ELEMS + a * KV_ELEMS +
                                         row * PITCH + c * 8) * 2),
                       gs[a] + row * D_ + c * 8);
        }
    }
}

// ===================== main attention kernel =====================
// 8 warps, each owns 16 q-rows x full 64 kv cols. blockIdx.z = kv split half.
__global__ void __launch_bounds__(256, 2)
attn_kernel(const int* __restrict__ mask) {
    extern __shared__ __half sm[];
    const int tid  = threadIdx.x;
    const int lane = tid & 31;
    const int w    = tid >> 5;
    const int qt   = blockIdx.x;
    const int b    = blockIdx.y;
    const int sp   = blockIdx.z;
    const int qbase = qt * BM;
    const int kt0   = sp * NT_CTA;

    const uint32_t smb = (uint32_t)__cvta_generic_to_shared(sm);

    // ---- async load Q tile, then KV tile kt0, one commit group
    {
        const __half* gq = g_q + ((size_t)b * LQ_ + qbase) * D_;
#pragma unroll
        for (int tt = 0; tt < 8; tt++) {
            int idx = tt * 256 + tid;
            int row = idx >> 4, c = idx & 15;
            cp_async16(smb + (uint32_t)((row * PITCH + c * 8) * 2),
                       gq + row * D_ + c * 8);
        }
    }
    load_kv(smb, b, kt0, 0, tid);
    cp_commit();

    // ---- per-thread ldmatrix base offsets
    const int l8  = lane & 7;
    const int grp = lane >> 3;
    const uint32_t aQ = smb + (uint32_t)(((w * 16 + (lane & 15)) * PITCH + (lane >> 4) * 8) * 2);
    const uint32_t b_off = (uint32_t)((((grp >> 1) * 8 + l8) * PITCH + (grp & 1) * 8) * 2);
    const uint32_t v_off = (uint32_t)((((grp & 1) * 8 + l8) * PITCH + (grp >> 1) * 8) * 2);

    // ---- mask / output row mapping (accumulator fragment rows)
    const int g0 = qbase + w * 16 + (lane >> 2);
    const int q2 = (lane & 3) * 2;
    const int* mrow0 = mask + ((size_t)b * LQ_ + g0) * LK_;
    const int* mrow1 = mrow0 + (size_t)8 * LK_;

    float oacc[16][4];
#pragma unroll
    for (int i = 0; i < 16; i++)
#pragma unroll
        for (int e = 0; e < 4; e++) oacc[i][e] = 0.0f;

#pragma unroll 1
    for (int lt = 0; lt < NT_CTA; ++lt) {
        const int kt = kt0 + lt;

        // mask LDGs first: independent of smem, latency hides under wait+MMAs
        int2 m0[8], m1[8];
#pragma unroll
        for (int j = 0; j < 8; j++) {
            int col = kt * BN + j * 8 + q2;
            m0[j] = *reinterpret_cast<const int2*>(mrow0 + col);
            m1[j] = *reinterpret_cast<const int2*>(mrow1 + col);
        }

        if (lt + 1 < NT_CTA) {
            load_kv(smb, b, kt + 1, (lt + 1) & 1, tid);
            cp_commit();
            cp_wait<1>();
        } else {
            cp_wait<0>();
        }
        __syncthreads();

        const uint32_t sK = smb + (uint32_t)((Q_ELEMS + (lt & 1) * STAGE_ELEMS) * 2);
        const uint32_t sV = sK + (uint32_t)(KV_ELEMS * 2);

        // ======== S = Q K^T  (16x64 per warp) ========
        float sacc[8][4];
#pragma unroll
        for (int j = 0; j < 8; j++)
#pragma unroll
            for (int e = 0; e < 4; e++) sacc[j][e] = 0.0f;

#pragma unroll
        for (int k16 = 0; k16 < 8; k16++) {
            uint32_t a[4];
            ldsm4(a, aQ + k16 * 32);
#pragma unroll
            for (int jp = 0; jp < 4; jp++) {
                uint32_t bb[4];
                ldsm4(bb, sK + b_off + (uint32_t)(jp * 16 * PITCH * 2) + k16 * 32);
                mma16816(sacc[2 * jp],     a, bb[0], bb[1]);
                mma16816(sacc[2 * jp + 1], a, bb[2], bb[3]);
            }
        }

        // ======== P = mask ? 0 : sigmoid(S*scale)  (tanh.approx) ========
#pragma unroll
        for (int j = 0; j < 8; j++) {
            sacc[j][0] = m0[j].x ? 0.0f : sigmoid_fast(sacc[j][0]);
            sacc[j][1] = m0[j].y ? 0.0f : sigmoid_fast(sacc[j][1]);
            sacc[j][2] = m1[j].x ? 0.0f : sigmoid_fast(sacc[j][2]);
            sacc[j][3] = m1[j].y ? 0.0f : sigmoid_fast(sacc[j][3]);
        }

        // ======== O += P V  (P from registers) ========
#pragma unroll
        for (int s = 0; s < 4; s++) {
            uint32_t pa[4];
            pa[0] = pack2h(sacc[2 * s][0],     sacc[2 * s][1]);
            pa[1] = pack2h(sacc[2 * s][2],     sacc[2 * s][3]);
            pa[2] = pack2h(sacc[2 * s + 1][0], sacc[2 * s + 1][1]);
            pa[3] = pack2h(sacc[2 * s + 1][2], sacc[2 * s + 1][3]);
#pragma unroll
            for (int jp = 0; jp < 8; jp++) {
                uint32_t vv[4];
                ldsm4t(vv, sV + v_off + (uint32_t)(s * 16 * PITCH * 2) + jp * 32);
                mma16816(oacc[2 * jp],     pa, vv[0], vv[1]);
                mma16816(oacc[2 * jp + 1], pa, vv[2], vv[3]);
            }
        }
        __syncthreads();
    }

    // ---- write partial O for this split
    float* o0 = g_part + (size_t)sp * PART_N + ((size_t)b * LQ_ + g0) * D_;
    float* o1 = o0 + (size_t)8 * D_;
#pragma unroll
    for (int jd = 0; jd < 16; jd++) {
        int col = jd * 8 + q2;
        *reinterpret_cast<float2*>(o0 + col) = make_float2(oacc[jd][0], oacc[jd][1]);
        *reinterpret_cast<float2*>(o1 + col) = make_float2(oacc[jd][2], oacc[jd][3]);
    }
}

// ===================== launch =====================
extern "C" void kernel_launch(void* const* d_in, const int* in_sizes, int n_in,
                              void* d_out, int out_size) {
    const float* q    = (const float*)d_in[0];
    const float* k    = (const float*)d_in[1];
    const float* v    = (const float*)d_in[2];
    const int*   mask = (const int*)d_in[3];
    float*       out  = (float*)d_out;

    cudaFuncSetAttribute(attn_kernel, cudaFuncAttributeMaxDynamicSharedMemorySize, SMEM_BYTES);

    // convert q,k,v to fp16
    split_kernel<<<dim3((B_ * LQ_ * D_ / 4) / 256, 3), 256>>>(q, k, v);

    // fused sigmoid-attention: 256 CTAs (16 q-tiles x 8 batch x 2 kv-splits)
    attn_kernel<<<dim3(LQ_ / BM, B_, NSPLIT), 256, SMEM_BYTES>>>(mask);

    // sum the two kv-split partials
    reduce_kernel<<<(PART_N / 4) / 256, 256>>>(out);
}

// round 7
// speedup vs baseline: 1.1669x; 1.1669x over previous
#include <cuda_runtime.h>
#include <cuda_fp16.h>
#include <cstdint>

// ===================== problem constants =====================
constexpr int B_  = 8;
constexpr int LQ_ = 2048;
constexpr int LK_ = 2048;
constexpr int D_  = 128;

constexpr int BM = 64;     // q rows per CTA
constexpr int BN = 64;     // kv rows per iteration
constexpr int PITCH = 136; // smem row pitch in fp16 elems (128 + 8 pad)
constexpr int NT = LK_ / BN; // 32 kv tiles

constexpr float SCALE = 0.08838834764831845f; // 1/sqrt(128)
constexpr float HALF_SCALE = 0.5f * SCALE;    // folded into Q at prep time

constexpr int Q_ELEMS     = BM * PITCH;            // 8704
constexpr int KV_ELEMS    = BN * PITCH;            // 8704
constexpr int STAGE_ELEMS = 2 * KV_ELEMS;          // K,V = 17408
constexpr int SMEM_ELEMS  = Q_ELEMS + 2 * STAGE_ELEMS; // 43520
constexpr int SMEM_BYTES  = SMEM_ELEMS * 2;        // 87040

// ===================== device scratch (fp16 casts) =====================
__device__ __half g_q[B_ * LQ_ * D_];   // pre-scaled by HALF_SCALE
__device__ __half g_k[B_ * LK_ * D_];
__device__ __half g_v[B_ * LK_ * D_];

// ===================== small asm helpers =====================
__device__ __forceinline__ void cp_async16(uint32_t dst, const void* src) {
    asm volatile("cp.async.cg.shared.global [%0], [%1], 16;" :: "r"(dst), "l"(src));
}
__device__ __forceinline__ void cp_commit() {
    asm volatile("cp.async.commit_group;");
}
template <int N>
__device__ __forceinline__ void cp_wait() {
    asm volatile("cp.async.wait_group %0;" :: "n"(N));
}
__device__ __forceinline__ void ldsm4(uint32_t* r, uint32_t addr) {
    asm volatile("ldmatrix.sync.aligned.m8n8.x4.shared.b16 {%0,%1,%2,%3}, [%4];"
                 : "=r"(r[0]), "=r"(r[1]), "=r"(r[2]), "=r"(r[3]) : "r"(addr));
}
__device__ __forceinline__ void ldsm4t(uint32_t* r, uint32_t addr) {
    asm volatile("ldmatrix.sync.aligned.m8n8.x4.trans.shared.b16 {%0,%1,%2,%3}, [%4];"
                 : "=r"(r[0]), "=r"(r[1]), "=r"(r[2]), "=r"(r[3]) : "r"(addr));
}
__device__ __forceinline__ void mma16816(float* c, const uint32_t* a, uint32_t b0, uint32_t b1) {
    asm volatile(
        "mma.sync.aligned.m16n8k16.row.col.f32.f16.f16.f32 "
        "{%0,%1,%2,%3}, {%4,%5,%6,%7}, {%8,%9}, {%0,%1,%2,%3};"
        : "+f"(c[0]), "+f"(c[1]), "+f"(c[2]), "+f"(c[3])
        : "r"(a[0]), "r"(a[1]), "r"(a[2]), "r"(a[3]), "r"(b0), "r"(b1));
}
// Q pre-scaled by SCALE/2, so sacc = x/2 where x = raw_score*SCALE.
// sigmoid(x) = 0.5*tanh(x/2) + 0.5 -> tanh.approx directly on sacc.
__device__ __forceinline__ float sigmoid_fast(float s) {
    float t;
    asm("tanh.approx.f32 %0, %1;" : "=f"(t) : "f"(s));
    return fmaf(t, 0.5f, 0.5f);
}
__device__ __forceinline__ uint32_t pack2h(float x, float y) {
    __half2 h = __floats2half2_rn(x, y);
    return *reinterpret_cast<uint32_t*>(&h);
}

// ===================== prep: fp32 -> fp16 (Q pre-scaled), 8 elems/thread =====================
__global__ void split_kernel(const float* __restrict__ q,
                             const float* __restrict__ k,
                             const float* __restrict__ v) {
    const int t = blockIdx.y;
    const float* s = (t == 0) ? q : (t == 1) ? k : v;
    __half* H = (t == 0) ? g_q : (t == 1) ? g_k : g_v;
    const float sc = (t == 0) ? HALF_SCALE : 1.0f;
    const int i = (blockIdx.x * blockDim.x + threadIdx.x) * 8;
    float4 a = *reinterpret_cast<const float4*>(s + i);
    float4 b = *reinterpret_cast<const float4*>(s + i + 4);
    __half2 h0 = __floats2half2_rn(a.x * sc, a.y * sc);
    __half2 h1 = __floats2half2_rn(a.z * sc, a.w * sc);
    __half2 h2 = __floats2half2_rn(b.x * sc, b.y * sc);
    __half2 h3 = __floats2half2_rn(b.z * sc, b.w * sc);
    uint4 o;
    o.x = *reinterpret_cast<uint32_t*>(&h0);
    o.y = *reinterpret_cast<uint32_t*>(&h1);
    o.z = *reinterpret_cast<uint32_t*>(&h2);
    o.w = *reinterpret_cast<uint32_t*>(&h3);
    *reinterpret_cast<uint4*>(H + i) = o;
}

// ===================== kv tile loader (K+V, 64 rows each) =====================
__device__ __forceinline__ void load_kv(uint32_t smb, int b, int kt, int stg, int tid) {
    const size_t base = ((size_t)b * LK_ + (size_t)kt * BN) * D_;
    const __half* gs[2] = { g_k + base, g_v + base };
#pragma unroll
    for (int a = 0; a < 2; a++) {
#pragma unroll
        for (int tt = 0; tt < 4; tt++) {
            int idx = tt * 256 + tid;
            int row = idx >> 4, c = idx & 15;
            cp_async16(smb + (uint32_t)((Q_ELEMS + stg * STAGE_ELEMS + a * KV_ELEMS +
                                         row * PITCH + c * 8) * 2),
                       gs[a] + row * D_ + c * 8);
        }
    }
}

// ===================== main attention kernel =====================
// 8 warps: mg = w&3 picks 16 q-rows (BM=64), ng = w>>2 picks 32 of the 64 kv cols.
__global__ void __launch_bounds__(256, 2)
attn_kernel(const int* __restrict__ mask, float* __restrict__ out) {
    extern __shared__ __half sm[];
    const int tid  = threadIdx.x;
    const int lane = tid & 31;
    const int w    = tid >> 5;
    const int mg   = w & 3;
    const int ng   = w >> 2;
    const int qt   = blockIdx.x;
    const int b    = blockIdx.y;
    const int qbase = qt * BM;

    const uint32_t smb = (uint32_t)__cvta_generic_to_shared(sm);

    // ---- async load Q tile, then KV stage 0, one commit group
    {
        const __half* gq = g_q + ((size_t)b * LQ_ + qbase) * D_;
#pragma unroll
        for (int tt = 0; tt < 4; tt++) {
            int idx = tt * 256 + tid;
            int row = idx >> 4, c = idx & 15;
            cp_async16(smb + (uint32_t)((row * PITCH + c * 8) * 2),
                       gq + row * D_ + c * 8);
        }
    }
    load_kv(smb, b, 0, 0, tid);
    cp_commit();

    // ---- per-thread ldmatrix base offsets
    const int l8  = lane & 7;
    const int grp = lane >> 3;
    const uint32_t aQ = smb + (uint32_t)(((mg * 16 + (lane & 15)) * PITCH + (lane >> 4) * 8) * 2);
    const uint32_t b_off = (uint32_t)((((grp >> 1) * 8 + l8) * PITCH + (grp & 1) * 8) * 2);
    const uint32_t v_off = (uint32_t)((((grp & 1) * 8 + l8) * PITCH + (grp >> 1) * 8) * 2);

    const int ncol0 = ng * 32;

    // ---- mask / output row mapping (accumulator fragment rows)
    const int g0 = qbase + mg * 16 + (lane >> 2);
    const int q2 = (lane & 3) * 2;
    const int* mrow0 = mask + ((size_t)b * LQ_ + g0) * LK_;
    const int* mrow1 = mrow0 + (size_t)8 * LK_;

    float oacc[16][4];
#pragma unroll
    for (int i = 0; i < 16; i++)
#pragma unroll
        for (int e = 0; e < 4; e++) oacc[i][e] = 0.0f;

#pragma unroll 1
    for (int kt = 0; kt < NT; ++kt) {
        // mask LDGs first: independent of smem state, latency hides under
        // the cp.async wait, the barrier, and the S MMAs.
        int2 m0[4], m1[4];
#pragma unroll
        for (int j = 0; j < 4; j++) {
            int col = kt * BN + ncol0 + j * 8 + q2;
            m0[j] = *reinterpret_cast<const int2*>(mrow0 + col);
            m1[j] = *reinterpret_cast<const int2*>(mrow1 + col);
        }

        if (kt + 1 < NT) {
            load_kv(smb, b, kt + 1, (kt + 1) & 1, tid);
            cp_commit();
            cp_wait<1>();
        } else {
            cp_wait<0>();
        }
        __syncthreads();

        const uint32_t sK = smb + (uint32_t)((Q_ELEMS + (kt & 1) * STAGE_ELEMS) * 2);
        const uint32_t sV = sK + (uint32_t)(KV_ELEMS * 2);

        // ======== S = Q K^T over this warp's 16x32 block ========
        float sacc[4][4];
#pragma unroll
        for (int j = 0; j < 4; j++)
#pragma unroll
            for (int e = 0; e < 4; e++) sacc[j][e] = 0.0f;

#pragma unroll
        for (int k16 = 0; k16 < 8; k16++) {
            uint32_t a[4];
            ldsm4(a, aQ + k16 * 32);
#pragma unroll
            for (int jp = 0; jp < 2; jp++) {
                uint32_t bb[4];
                ldsm4(bb, sK + b_off + (uint32_t)(((ncol0 + jp * 16) * PITCH) * 2) + k16 * 32);
                mma16816(sacc[2 * jp],     a, bb[0], bb[1]);
                mma16816(sacc[2 * jp + 1], a, bb[2], bb[3]);
            }
        }

        // ======== P = mask ? 0 : sigmoid (tanh.approx, scale pre-folded) ========
#pragma unroll
        for (int j = 0; j < 4; j++) {
            sacc[j][0] = m0[j].x ? 0.0f : sigmoid_fast(sacc[j][0]);
            sacc[j][1] = m0[j].y ? 0.0f : sigmoid_fast(sacc[j][1]);
            sacc[j][2] = m1[j].x ? 0.0f : sigmoid_fast(sacc[j][2]);
            sacc[j][3] = m1[j].y ? 0.0f : sigmoid_fast(sacc[j][3]);
        }

        // ======== O += P V over this warp's 32 kv rows ========
#pragma unroll
        for (int s = 0; s < 2; s++) {
            uint32_t pa[4];
            pa[0] = pack2h(sacc[2 * s][0],     sacc[2 * s][1]);
            pa[1] = pack2h(sacc[2 * s][2],     sacc[2 * s][3]);
            pa[2] = pack2h(sacc[2 * s + 1][0], sacc[2 * s + 1][1]);
            pa[3] = pack2h(sacc[2 * s + 1][2], sacc[2 * s + 1][3]);
#pragma unroll
            for (int jp = 0; jp < 8; jp++) {
                uint32_t vv[4];
                ldsm4t(vv, sV + v_off + (uint32_t)(((ncol0 + s * 16) * PITCH) * 2) + jp * 32);
                mma16816(oacc[2 * jp],     pa, vv[0], vv[1]);
                mma16816(oacc[2 * jp + 1], pa, vv[2], vv[3]);
            }
        }
        __syncthreads();
    }

    // ---- reduce the two kv-column halves through smem, then write O
    float* smf = reinterpret_cast<float*>(sm);
    const int r0 = lane >> 2;
    if (ng == 1) {
#pragma unroll
        for (int jd = 0; jd < 16; jd++) {
            int col = jd * 8 + q2;
            float* p0 = smf + (mg * 16 + r0) * 128 + col;
            float* p1 = smf + (mg * 16 + r0 + 8) * 128 + col;
            p0[0] = oacc[jd][0]; p0[1] = oacc[jd][1];
            p1[0] = oacc[jd][2]; p1[1] = oacc[jd][3];
        }
    }
    __syncthreads();
    if (ng == 0) {
        float* o0 = out + ((size_t)b * LQ_ + g0) * D_;
        float* o1 = o0 + (size_t)8 * D_;
#pragma unroll
        for (int jd = 0; jd < 16; jd++) {
            int col = jd * 8 + q2;
            const float* p0 = smf + (mg * 16 + r0) * 128 + col;
            const float* p1 = smf + (mg * 16 + r0 + 8) * 128 + col;
            *reinterpret_cast<float2*>(o0 + col) =
                make_float2(oacc[jd][0] + p0[0], oacc[jd][1] + p0[1]);
            *reinterpret_cast<float2*>(o1 + col) =
                make_float2(oacc[jd][2] + p1[0], oacc[jd][3] + p1[1]);
        }
    }
}

// ===================== launch =====================
extern "C" void kernel_launch(void* const* d_in, const int* in_sizes, int n_in,
                              void* d_out, int out_size) {
    const float* q    = (const float*)d_in[0];
    const float* k    = (const float*)d_in[1];
    const float* v    = (const float*)d_in[2];
    const int*   mask = (const int*)d_in[3];
    float*       out  = (float*)d_out;

    cudaFuncSetAttribute(attn_kernel, cudaFuncAttributeMaxDynamicSharedMemorySize, SMEM_BYTES);

    // convert q,k,v to fp16 (Q pre-scaled by SCALE/2); 8 elems/thread, STG.128
    split_kernel<<<dim3((B_ * LQ_ * D_ / 8) / 256, 3), 256>>>(q, k, v);

    // fused sigmoid-attention: 256 CTAs -> 2 CTAs/SM, 16 warps/SM
    attn_kernel<<<dim3(LQ_ / BM, B_), 256, SMEM_BYTES>>>(mask, out);
}

// round 8
// speedup vs baseline: 1.1743x; 1.0064x over previous
#include <cuda_runtime.h>
#include <cuda_fp16.h>
#include <cstdint>

// ===================== problem constants =====================
constexpr int B_  = 8;
constexpr int LQ_ = 2048;
constexpr int LK_ = 2048;
constexpr int D_  = 128;

constexpr int BM = 64;     // q rows per CTA
constexpr int BN = 64;     // kv rows per iteration
constexpr int PITCH = 136; // smem row pitch in fp16 elems (128 + 8 pad)
constexpr int NT = LK_ / BN; // 32 kv tiles

constexpr float SCALE = 0.08838834764831845f; // 1/sqrt(128)
constexpr float HALF_SCALE = 0.5f * SCALE;    // folded into Q at prep time

constexpr int Q_ELEMS     = BM * PITCH;            // 8704
constexpr int KV_ELEMS    = BN * PITCH;            // 8704
constexpr int STAGE_ELEMS = 2 * KV_ELEMS;          // K,V = 17408
constexpr int SMEM_ELEMS  = Q_ELEMS + 2 * STAGE_ELEMS; // 43520
constexpr int SMEM_BYTES  = SMEM_ELEMS * 2;        // 87040

// ===================== device scratch (fp16 casts) =====================
__device__ __half g_q[B_ * LQ_ * D_];   // pre-scaled by HALF_SCALE
__device__ __half g_k[B_ * LK_ * D_];
__device__ __half g_v[B_ * LK_ * D_];

// ===================== small asm helpers =====================
__device__ __forceinline__ void cp_async16(uint32_t dst, const void* src) {
    asm volatile("cp.async.cg.shared.global [%0], [%1], 16;" :: "r"(dst), "l"(src));
}
__device__ __forceinline__ void cp_commit() {
    asm volatile("cp.async.commit_group;");
}
template <int N>
__device__ __forceinline__ void cp_wait() {
    asm volatile("cp.async.wait_group %0;" :: "n"(N));
}
__device__ __forceinline__ void ldsm4(uint32_t* r, uint32_t addr) {
    asm volatile("ldmatrix.sync.aligned.m8n8.x4.shared.b16 {%0,%1,%2,%3}, [%4];"
                 : "=r"(r[0]), "=r"(r[1]), "=r"(r[2]), "=r"(r[3]) : "r"(addr));
}
__device__ __forceinline__ void ldsm4t(uint32_t* r, uint32_t addr) {
    asm volatile("ldmatrix.sync.aligned.m8n8.x4.trans.shared.b16 {%0,%1,%2,%3}, [%4];"
                 : "=r"(r[0]), "=r"(r[1]), "=r"(r[2]), "=r"(r[3]) : "r"(addr));
}
__device__ __forceinline__ void mma16816(float* c, const uint32_t* a, uint32_t b0, uint32_t b1) {
    asm volatile(
        "mma.sync.aligned.m16n8k16.row.col.f32.f16.f16.f32 "
        "{%0,%1,%2,%3}, {%4,%5,%6,%7}, {%8,%9}, {%0,%1,%2,%3};"
        : "+f"(c[0]), "+f"(c[1]), "+f"(c[2]), "+f"(c[3])
        : "r"(a[0]), "r"(a[1]), "r"(a[2]), "r"(a[3]), "r"(b0), "r"(b1));
}
// Q pre-scaled by SCALE/2, so sacc = x/2 where x = raw_score*SCALE.
// sigmoid(x) = 0.5*tanh(x/2) + 0.5 -> tanh.approx directly on sacc.
__device__ __forceinline__ float sigmoid_fast(float s) {
    float t;
    asm("tanh.approx.f32 %0, %1;" : "=f"(t) : "f"(s));
    return fmaf(t, 0.5f, 0.5f);
}
__device__ __forceinline__ uint32_t pack2h(float x, float y) {
    __half2 h = __floats2half2_rn(x, y);
    return *reinterpret_cast<uint32_t*>(&h);
}

// ===================== prep: fp32 -> fp16 (Q pre-scaled), 8 elems/thread =====================
__global__ void split_kernel(const float* __restrict__ q,
                             const float* __restrict__ k,
                             const float* __restrict__ v) {
    const int t = blockIdx.y;
    const float* s = (t == 0) ? q : (t == 1) ? k : v;
    __half* H = (t == 0) ? g_q : (t == 1) ? g_k : g_v;
    const float sc = (t == 0) ? HALF_SCALE : 1.0f;
    const int i = (blockIdx.x * blockDim.x + threadIdx.x) * 8;
    float4 a = *reinterpret_cast<const float4*>(s + i);
    float4 b = *reinterpret_cast<const float4*>(s + i + 4);
    __half2 h0 = __floats2half2_rn(a.x * sc, a.y * sc);
    __half2 h1 = __floats2half2_rn(a.z * sc, a.w * sc);
    __half2 h2 = __floats2half2_rn(b.x * sc, b.y * sc);
    __half2 h3 = __floats2half2_rn(b.z * sc, b.w * sc);
    uint4 o;
    o.x = *reinterpret_cast<uint32_t*>(&h0);
    o.y = *reinterpret_cast<uint32_t*>(&h1);
    o.z = *reinterpret_cast<uint32_t*>(&h2);
    o.w = *reinterpret_cast<uint32_t*>(&h3);
    *reinterpret_cast<uint4*>(H + i) = o;
}

// ===================== kv tile loader (K+V, 64 rows each) =====================
__device__ __forceinline__ void load_kv(uint32_t smb, int b, int kt, int stg, int tid) {
    const size_t base = ((size_t)b * LK_ + (size_t)kt * BN) * D_;
    const __half* gs[2] = { g_k + base, g_v + base };
#pragma unroll
    for (int a = 0; a < 2; a++) {
#pragma unroll
        for (int tt = 0; tt < 4; tt++) {
            int idx = tt * 256 + tid;
            int row = idx >> 4, c = idx & 15;
            cp_async16(smb + (uint32_t)((Q_ELEMS + stg * STAGE_ELEMS + a * KV_ELEMS +
                                         row * PITCH + c * 8) * 2),
                       gs[a] + row * D_ + c * 8);
        }
    }
}

// ===================== main attention kernel =====================
// 8 warps: mg = w&3 picks 16 q-rows (BM=64), ng = w>>2 picks 32 of the 64 kv cols.
__global__ void __launch_bounds__(256, 2)
attn_kernel(const int* __restrict__ mask, float* __restrict__ out) {
    extern __shared__ __half sm[];
    const int tid  = threadIdx.x;
    const int lane = tid & 31;
    const int w    = tid >> 5;
    const int mg   = w & 3;
    const int ng   = w >> 2;
    const int qt   = blockIdx.x;
    const int b    = blockIdx.y;
    const int qbase = qt * BM;

    const uint32_t smb = (uint32_t)__cvta_generic_to_shared(sm);

    // ---- async load Q tile, then KV stage 0, one commit group
    {
        const __half* gq = g_q + ((size_t)b * LQ_ + qbase) * D_;
#pragma unroll
        for (int tt = 0; tt < 4; tt++) {
            int idx = tt * 256 + tid;
            int row = idx >> 4, c = idx & 15;
            cp_async16(smb + (uint32_t)((row * PITCH + c * 8) * 2),
                       gq + row * D_ + c * 8);
        }
    }
    load_kv(smb, b, 0, 0, tid);
    cp_commit();

    // ---- per-thread ldmatrix base offsets
    const int l8  = lane & 7;
    const int grp = lane >> 3;
    const uint32_t aQ = smb + (uint32_t)(((mg * 16 + (lane & 15)) * PITCH + (lane >> 4) * 8) * 2);
    const uint32_t b_off = (uint32_t)((((grp >> 1) * 8 + l8) * PITCH + (grp & 1) * 8) * 2);
    const uint32_t v_off = (uint32_t)((((grp & 1) * 8 + l8) * PITCH + (grp >> 1) * 8) * 2);

    const int ncol0 = ng * 32;

    // ---- mask / output row mapping (accumulator fragment rows)
    const int g0 = qbase + mg * 16 + (lane >> 2);
    const int q2 = (lane & 3) * 2;
    const int* mrow0 = mask + ((size_t)b * LQ_ + g0) * LK_;
    const int* mrow1 = mrow0 + (size_t)8 * LK_;

    float oacc[16][4];
#pragma unroll
    for (int i = 0; i < 16; i++)
#pragma unroll
        for (int e = 0; e < 4; e++) oacc[i][e] = 0.0f;

#pragma unroll 1
    for (int kt = 0; kt < NT; ++kt) {
        // mask LDGs first: independent of smem state, latency hides under
        // the cp.async wait, the barrier, and the S MMAs.
        int2 m0[4], m1[4];
#pragma unroll
        for (int j = 0; j < 4; j++) {
            int col = kt * BN + ncol0 + j * 8 + q2;
            m0[j] = *reinterpret_cast<const int2*>(mrow0 + col);
            m1[j] = *reinterpret_cast<const int2*>(mrow1 + col);
        }

        if (kt + 1 < NT) {
            load_kv(smb, b, kt + 1, (kt + 1) & 1, tid);
            cp_commit();
            cp_wait<1>();
        } else {
            cp_wait<0>();
        }
        __syncthreads();

        const uint32_t sK = smb + (uint32_t)((Q_ELEMS + (kt & 1) * STAGE_ELEMS) * 2);
        const uint32_t sV = sK + (uint32_t)(KV_ELEMS * 2);

        // ======== S = Q K^T over this warp's 16x32 block ========
        float sacc[4][4];
#pragma unroll
        for (int j = 0; j < 4; j++)
#pragma unroll
            for (int e = 0; e < 4; e++) sacc[j][e] = 0.0f;

#pragma unroll
        for (int k16 = 0; k16 < 8; k16++) {
            uint32_t a[4];
            ldsm4(a, aQ + k16 * 32);
#pragma unroll
            for (int jp = 0; jp < 2; jp++) {
                uint32_t bb[4];
                ldsm4(bb, sK + b_off + (uint32_t)(((ncol0 + jp * 16) * PITCH) * 2) + k16 * 32);
                mma16816(sacc[2 * jp],     a, bb[0], bb[1]);
                mma16816(sacc[2 * jp + 1], a, bb[2], bb[3]);
            }
        }

        // ======== P = mask ? 0 : sigmoid (tanh.approx, scale pre-folded) ========
#pragma unroll
        for (int j = 0; j < 4; j++) {
            sacc[j][0] = m0[j].x ? 0.0f : sigmoid_fast(sacc[j][0]);
            sacc[j][1] = m0[j].y ? 0.0f : sigmoid_fast(sacc[j][1]);
            sacc[j][2] = m1[j].x ? 0.0f : sigmoid_fast(sacc[j][2]);
            sacc[j][3] = m1[j].y ? 0.0f : sigmoid_fast(sacc[j][3]);
        }

        // ======== O += P V over this warp's 32 kv rows ========
#pragma unroll
        for (int s = 0; s < 2; s++) {
            uint32_t pa[4];
            pa[0] = pack2h(sacc[2 * s][0],     sacc[2 * s][1]);
            pa[1] = pack2h(sacc[2 * s][2],     sacc[2 * s][3]);
            pa[2] = pack2h(sacc[2 * s + 1][0], sacc[2 * s + 1][1]);
            pa[3] = pack2h(sacc[2 * s + 1][2], sacc[2 * s + 1][3]);
#pragma unroll
            for (int jp = 0; jp < 8; jp++) {
                uint32_t vv[4];
                ldsm4t(vv, sV + v_off + (uint32_t)(((ncol0 + s * 16) * PITCH) * 2) + jp * 32);
                mma16816(oacc[2 * jp],     pa, vv[0], vv[1]);
                mma16816(oacc[2 * jp + 1], pa, vv[2], vv[3]);
            }
        }
        __syncthreads();
    }

    // ---- reduce the two kv-column halves through smem, then write O
    float* smf = reinterpret_cast<float*>(sm);
    const int r0 = lane >> 2;
    if (ng == 1) {
#pragma unroll
        for (int jd = 0; jd < 16; jd++) {
            int col = jd * 8 + q2;
            float* p0 = smf + (mg * 16 + r0) * 128 + col;
            float* p1 = smf + (mg * 16 + r0 + 8) * 128 + col;
            p0[0] = oacc[jd][0]; p0[1] = oacc[jd][1];
            p1[0] = oacc[jd][2]; p1[1] = oacc[jd][3];
        }
    }
    __syncthreads();
    if (ng == 0) {
        float* o0 = out + ((size_t)b * LQ_ + g0) * D_;
        float* o1 = o0 + (size_t)8 * D_;
#pragma unroll
        for (int jd = 0; jd < 16; jd++) {
            int col = jd * 8 + q2;
            const float* p0 = smf + (mg * 16 + r0) * 128 + col;
            const float* p1 = smf + (mg * 16 + r0 + 8) * 128 + col;
            *reinterpret_cast<float2*>(o0 + col) =
                make_float2(oacc[jd][0] + p0[0], oacc[jd][1] + p0[1]);
            *reinterpret_cast<float2*>(o1 + col) =
                make_float2(oacc[jd][2] + p1[0], oacc[jd][3] + p1[1]);
        }
    }
}

// ===================== launch =====================
extern "C" void kernel_launch(void* const* d_in, const int* in_sizes, int n_in,
                              void* d_out, int out_size) {
    const float* q    = (const float*)d_in[0];
    const float* k    = (const float*)d_in[1];
    const float* v    = (const float*)d_in[2];
    const int*   mask = (const int*)d_in[3];
    float*       out  = (float*)d_out;

    cudaFuncSetAttribute(attn_kernel, cudaFuncAttributeMaxDynamicSharedMemorySize, SMEM_BYTES);

    // convert q,k,v to fp16 (Q pre-scaled by SCALE/2); 8 elems/thread, STG.128
    split_kernel<<<dim3((B_ * LQ_ * D_ / 8) / 256, 3), 256>>>(q, k, v);

    // fused sigmoid-attention: 256 CTAs -> 2 CTAs/SM, 16 warps/SM
    attn_kernel<<<dim3(LQ_ / BM, B_), 256, SMEM_BYTES>>>(mask, out);
}

// round 9
// speedup vs baseline: 1.2520x; 1.0662x over previous
#include <cuda_runtime.h>
#include <cuda_fp16.h>
#include <cstdint>

// ===================== problem constants =====================
constexpr int B_  = 8;
constexpr int LQ_ = 2048;
constexpr int LK_ = 2048;
constexpr int D_  = 128;

constexpr int BM = 64;     // q rows per CTA
constexpr int BN = 64;     // kv rows per iteration
constexpr int NT = LK_ / BN; // 32 kv tiles

constexpr float SCALE = 0.08838834764831845f; // 1/sqrt(128)
constexpr float HALF_SCALE = 0.5f * SCALE;    // folded into Q at prep time

// ---- smem: swizzled, no padding. Row = 128 fp16 = 256B.
constexpr int SM_Q        = 0;
constexpr int TILE_BYTES  = 64 * 256;            // 16384 (one 64x128 fp16 tile)
constexpr int SM_KV       = TILE_BYTES;          // Q occupies one tile
constexpr int STAGE_BYTES = 2 * TILE_BYTES;      // K + V
constexpr int NSTAGE      = 3;
constexpr int SMEM_BYTES  = SM_KV + NSTAGE * STAGE_BYTES; // 114688 -> 2 CTAs/SM

// ===================== device scratch (fp16 casts) =====================
__device__ __half g_q[B_ * LQ_ * D_];   // pre-scaled by HALF_SCALE
__device__ __half g_k[B_ * LK_ * D_];
__device__ __half g_v[B_ * LK_ * D_];

// ===================== small asm helpers =====================
__device__ __forceinline__ void cp_async16(uint32_t dst, const void* src) {
    asm volatile("cp.async.cg.shared.global [%0], [%1], 16;" :: "r"(dst), "l"(src));
}
__device__ __forceinline__ void cp_commit() {
    asm volatile("cp.async.commit_group;");
}
template <int N>
__device__ __forceinline__ void cp_wait() {
    asm volatile("cp.async.wait_group %0;" :: "n"(N));
}
__device__ __forceinline__ void ldsm4(uint32_t* r, uint32_t addr) {
    asm volatile("ldmatrix.sync.aligned.m8n8.x4.shared.b16 {%0,%1,%2,%3}, [%4];"
                 : "=r"(r[0]), "=r"(r[1]), "=r"(r[2]), "=r"(r[3]) : "r"(addr));
}
__device__ __forceinline__ void ldsm4t(uint32_t* r, uint32_t addr) {
    asm volatile("ldmatrix.sync.aligned.m8n8.x4.trans.shared.b16 {%0,%1,%2,%3}, [%4];"
                 : "=r"(r[0]), "=r"(r[1]), "=r"(r[2]), "=r"(r[3]) : "r"(addr));
}
__device__ __forceinline__ void mma16816(float* c, const uint32_t* a, uint32_t b0, uint32_t b1) {
    asm volatile(
        "mma.sync.aligned.m16n8k16.row.col.f32.f16.f16.f32 "
        "{%0,%1,%2,%3}, {%4,%5,%6,%7}, {%8,%9}, {%0,%1,%2,%3};"
        : "+f"(c[0]), "+f"(c[1]), "+f"(c[2]), "+f"(c[3])
        : "r"(a[0]), "r"(a[1]), "r"(a[2]), "r"(a[3]), "r"(b0), "r"(b1));
}
// Q pre-scaled by SCALE/2: sigmoid(x) = 0.5*tanh(x/2)+0.5, tanh.approx on sacc.
__device__ __forceinline__ float sigmoid_fast(float s) {
    float t;
    asm("tanh.approx.f32 %0, %1;" : "=f"(t) : "f"(s));
    return fmaf(t, 0.5f, 0.5f);
}
__device__ __forceinline__ uint32_t pack2h(float x, float y) {
    __half2 h = __floats2half2_rn(x, y);
    return *reinterpret_cast<uint32_t*>(&h);
}
// swizzled byte offset within a 64x128 fp16 tile: row 256B, 16B unit ^= row&7
__device__ __forceinline__ uint32_t sw_off(int row, int c16) {
    return (uint32_t)(row * 256 + ((c16 ^ (row & 7)) << 4));
}

// ===================== prep: fp32 -> fp16 (Q pre-scaled), 8 elems/thread =====================
__global__ void split_kernel(const float* __restrict__ q,
                             const float* __restrict__ k,
                             const float* __restrict__ v) {
    const int t = blockIdx.y;
    const float* s = (t == 0) ? q : (t == 1) ? k : v;
    __half* H = (t == 0) ? g_q : (t == 1) ? g_k : g_v;
    const float sc = (t == 0) ? HALF_SCALE : 1.0f;
    const int i = (blockIdx.x * blockDim.x + threadIdx.x) * 8;
    float4 a = *reinterpret_cast<const float4*>(s + i);
    float4 b = *reinterpret_cast<const float4*>(s + i + 4);
    __half2 h0 = __floats2half2_rn(a.x * sc, a.y * sc);
    __half2 h1 = __floats2half2_rn(a.z * sc, a.w * sc);
    __half2 h2 = __floats2half2_rn(b.x * sc, b.y * sc);
    __half2 h3 = __floats2half2_rn(b.z * sc, b.w * sc);
    uint4 o;
    o.x = *reinterpret_cast<uint32_t*>(&h0);
    o.y = *reinterpret_cast<uint32_t*>(&h1);
    o.z = *reinterpret_cast<uint32_t*>(&h2);
    o.w = *reinterpret_cast<uint32_t*>(&h3);
    *reinterpret_cast<uint4*>(H + i) = o;
}

// ===================== kv tile loader (K+V, 64 rows each, swizzled) =====================
__device__ __forceinline__ void load_kv(uint32_t smb, int b, int kt, int stg, int tid) {
    const size_t base = ((size_t)b * LK_ + (size_t)kt * BN) * D_;
    const __half* gs[2] = { g_k + base, g_v + base };
    const uint32_t sbase = smb + (uint32_t)(SM_KV + stg * STAGE_BYTES);
#pragma unroll
    for (int a = 0; a < 2; a++) {
#pragma unroll
        for (int tt = 0; tt < 4; tt++) {
            int idx = tt * 256 + tid;          // 1024 chunks of 16B per tile
            int row = idx >> 4, c16 = idx & 15;
            cp_async16(sbase + (uint32_t)(a * TILE_BYTES) + sw_off(row, c16),
                       gs[a] + (size_t)row * D_ + c16 * 8);
        }
    }
}

// ===================== main attention kernel =====================
// 8 warps: mg = w&3 -> 16 q-rows, ng = w>>2 -> 32 of 64 kv cols.
// 3-stage cp.async pipeline, one __syncthreads per iteration.
__global__ void __launch_bounds__(256, 2)
attn_kernel(const int* __restrict__ mask, float* __restrict__ out) {
    extern __shared__ __half sm[];
    const int tid  = threadIdx.x;
    const int lane = tid & 31;
    const int w    = tid >> 5;
    const int mg   = w & 3;
    const int ng   = w >> 2;
    const int qt   = blockIdx.x;
    const int b    = blockIdx.y;
    const int qbase = qt * BM;

    const uint32_t smb = (uint32_t)__cvta_generic_to_shared(sm);

    // ---- prologue: G0 = Q + KV tile0, G1 = KV tile1
    {
        const __half* gq = g_q + ((size_t)b * LQ_ + qbase) * D_;
#pragma unroll
        for (int tt = 0; tt < 4; tt++) {
            int idx = tt * 256 + tid;
            int row = idx >> 4, c16 = idx & 15;
            cp_async16(smb + SM_Q + sw_off(row, c16), gq + (size_t)row * D_ + c16 * 8);
        }
    }
    load_kv(smb, b, 0, 0, tid);
    cp_commit();                       // G0
    load_kv(smb, b, 1, 1, tid);
    cp_commit();                       // G1

    // ---- per-thread fragment coordinates
    const int l8  = lane & 7;
    const int grp = lane >> 3;
    const int hi  = lane >> 4;                 // Q c16 half
    const int rowq = mg * 16 + (lane & 15);
    const uint32_t qrow = smb + SM_Q + (uint32_t)(rowq * 256);
    const int qx = rowq & 7;
    const int g1 = grp & 1;
    const int ncol0 = ng * 32;
    const int krow0 = ncol0 + (grp >> 1) * 8 + l8;      // K fragment row (+jp*16)
    const int vrow0 = ncol0 + g1 * 8 + l8;              // V fragment row (+s*16)
    const int vc0   = grp >> 1;                         // V c16 base (+jp*2)

    // ---- mask / output row mapping
    const int g0 = qbase + mg * 16 + (lane >> 2);
    const int q2 = (lane & 3) * 2;
    const int* mrow0 = mask + ((size_t)b * LQ_ + g0) * LK_;
    const int* mrow1 = mrow0 + (size_t)8 * LK_;

    float oacc[16][4];
#pragma unroll
    for (int i = 0; i < 16; i++)
#pragma unroll
        for (int e = 0; e < 4; e++) oacc[i][e] = 0.0f;

#pragma unroll 1
    for (int kt = 0; kt < NT; ++kt) {
        // mask LDGs first (independent; latency hides under wait+MMAs)
        int2 m0[4], m1[4];
#pragma unroll
        for (int j = 0; j < 4; j++) {
            int col = kt * BN + ncol0 + j * 8 + q2;
            m0[j] = *reinterpret_cast<const int2*>(mrow0 + col);
            m1[j] = *reinterpret_cast<const int2*>(mrow1 + col);
        }

        if (kt + 1 < NT) cp_wait<1>(); else cp_wait<0>();
        __syncthreads();   // stage kt visible to all; iter kt-1 reads finished

        if (kt + 2 < NT) {
            load_kv(smb, b, kt + 2, (kt + 2) % 3, tid);
            cp_commit();
        }

        const uint32_t sK = smb + (uint32_t)(SM_KV + (kt % 3) * STAGE_BYTES);
        const uint32_t sV = sK + (uint32_t)TILE_BYTES;

        // ======== S = Q K^T over this warp's 16x32 block ========
        float sacc[4][4];
#pragma unroll
        for (int j = 0; j < 4; j++)
#pragma unroll
            for (int e = 0; e < 4; e++) sacc[j][e] = 0.0f;

#pragma unroll
        for (int k16 = 0; k16 < 8; k16++) {
            uint32_t a[4];
            ldsm4(a, qrow + (uint32_t)((((k16 * 2 + hi) ^ qx) << 4)));
#pragma unroll
            for (int jp = 0; jp < 2; jp++) {
                uint32_t bb[4];
                ldsm4(bb, sK + (uint32_t)((krow0 + jp * 16) * 256 +
                                          (((k16 * 2 + g1) ^ l8) << 4)));
                mma16816(sacc[2 * jp],     a, bb[0], bb[1]);
                mma16816(sacc[2 * jp + 1], a, bb[2], bb[3]);
            }
        }

        // ======== P = mask ? 0 : sigmoid (tanh.approx, scale pre-folded) ========
#pragma unroll
        for (int j = 0; j < 4; j++) {
            sacc[j][0] = m0[j].x ? 0.0f : sigmoid_fast(sacc[j][0]);
            sacc[j][1] = m0[j].y ? 0.0f : sigmoid_fast(sacc[j][1]);
            sacc[j][2] = m1[j].x ? 0.0f : sigmoid_fast(sacc[j][2]);
            sacc[j][3] = m1[j].y ? 0.0f : sigmoid_fast(sacc[j][3]);
        }

        // ======== O += P V over this warp's 32 kv rows ========
#pragma unroll
        for (int s = 0; s < 2; s++) {
            uint32_t pa[4];
            pa[0] = pack2h(sacc[2 * s][0],     sacc[2 * s][1]);
            pa[1] = pack2h(sacc[2 * s][2],     sacc[2 * s][3]);
            pa[2] = pack2h(sacc[2 * s + 1][0], sacc[2 * s + 1][1]);
            pa[3] = pack2h(sacc[2 * s + 1][2], sacc[2 * s + 1][3]);
            const uint32_t vr = sV + (uint32_t)((vrow0 + s * 16) * 256);
#pragma unroll
            for (int jp = 0; jp < 8; jp++) {
                uint32_t vv[4];
                ldsm4t(vv, vr + (uint32_t)((((vc0 + jp * 2) ^ l8) << 4)));
                mma16816(oacc[2 * jp],     pa, vv[0], vv[1]);
                mma16816(oacc[2 * jp + 1], pa, vv[2], vv[3]);
            }
        }
        // no trailing barrier: next iter's top barrier fences stage reuse
    }

    // ---- reduce the two kv-column halves through smem, then write O
    __syncthreads();   // all warps out of the mainloop before smem reuse
    float* smf = reinterpret_cast<float*>(sm);
    const int r0 = lane >> 2;
    if (ng == 1) {
#pragma unroll
        for (int jd = 0; jd < 16; jd++) {
            int col = jd * 8 + q2;
            float* p0 = smf + (mg * 16 + r0) * 128 + col;
            float* p1 = smf + (mg * 16 + r0 + 8) * 128 + col;
            p0[0] = oacc[jd][0]; p0[1] = oacc[jd][1];
            p1[0] = oacc[jd][2]; p1[1] = oacc[jd][3];
        }
    }
    __syncthreads();
    if (ng == 0) {
        float* o0 = out + ((size_t)b * LQ_ + g0) * D_;
        float* o1 = o0 + (size_t)8 * D_;
#pragma unroll
        for (int jd = 0; jd < 16; jd++) {
            int col = jd * 8 + q2;
            const float* p0 = smf + (mg * 16 + r0) * 128 + col;
            const float* p1 = smf + (mg * 16 + r0 + 8) * 128 + col;
            *reinterpret_cast<float2*>(o0 + col) =
                make_float2(oacc[jd][0] + p0[0], oacc[jd][1] + p0[1]);
            *reinterpret_cast<float2*>(o1 + col) =
                make_float2(oacc[jd][2] + p1[0], oacc[jd][3] + p1[1]);
        }
    }
}

// ===================== launch =====================
extern "C" void kernel_launch(void* const* d_in, const int* in_sizes, int n_in,
                              void* d_out, int out_size) {
    const float* q    = (const float*)d_in[0];
    const float* k    = (const float*)d_in[1];
    const float* v    = (const float*)d_in[2];
    const int*   mask = (const int*)d_in[3];
    float*       out  = (float*)d_out;

    cudaFuncSetAttribute(attn_kernel, cudaFuncAttributeMaxDynamicSharedMemorySize, SMEM_BYTES);

    // convert q,k,v to fp16 (Q pre-scaled by SCALE/2)
    split_kernel<<<dim3((B_ * LQ_ * D_ / 8) / 256, 3), 256>>>(q, k, v);

    // fused sigmoid-attention: 256 CTAs, 2 CTAs/SM, 3-stage pipeline
    attn_kernel<<<dim3(LQ_ / BM, B_), 256, SMEM_BYTES>>>(mask, out);
}